// round 1
// baseline (speedup 1.0000x reference)
#include <cuda_runtime.h>

#define BB   8
#define MM   40000
#define FIN  64
#define KK   6
#define FOUT 64
#define NNZ  320000
#define CW   512    // field width = FIN*BB
#define CW4  128    // in float4

// Scratch (static device allocs are the sanctioned workaround)
__device__ float g_T[KK][MM][CW];      // ~491.5 MB: all Chebyshev fields
__device__ int   g_rowptr[MM + 1];
__device__ int   g_counts[MM];
__device__ int   g_off[MM];
__device__ int   g_colS[NNZ];
__device__ float g_valS[NNZ];

// ---------------------------------------------------------------------------
// CSR build
// ---------------------------------------------------------------------------
__global__ void k_zero_counts() {
    int i = blockIdx.x * blockDim.x + threadIdx.x;
    if (i < MM) g_counts[i] = 0;
}

__global__ void k_hist(const int* __restrict__ rows) {
    int e = blockIdx.x * blockDim.x + threadIdx.x;
    if (e < NNZ) atomicAdd(&g_counts[rows[e]], 1);
}

// Single-block exclusive scan over 40000 counts (1024 threads x 40 elems)
__global__ void k_scan() {
    __shared__ int s[1024];
    const int EPT = (MM + 1023) / 1024;  // 40
    int t = threadIdx.x;
    int base = t * EPT;

    int sum = 0;
    for (int i = 0; i < EPT; i++) {
        int idx = base + i;
        if (idx < MM) sum += g_counts[idx];
    }
    s[t] = sum;
    __syncthreads();

    // Hillis-Steele inclusive scan
    for (int off = 1; off < 1024; off <<= 1) {
        int v = 0;
        if (t >= off) v = s[t - off];
        __syncthreads();
        s[t] += v;
        __syncthreads();
    }

    int run = s[t] - sum;  // exclusive prefix for this thread's chunk
    for (int i = 0; i < EPT; i++) {
        int idx = base + i;
        if (idx < MM) {
            int c = g_counts[idx];
            g_rowptr[idx] = run;
            g_off[idx]    = run;
            run += c;
        }
    }
    if (t == 0) g_rowptr[MM] = NNZ;
}

__global__ void k_scatter(const int* __restrict__ rows,
                          const int* __restrict__ cols,
                          const float* __restrict__ vals) {
    int e = blockIdx.x * blockDim.x + threadIdx.x;
    if (e < NNZ) {
        int r = rows[e];
        int p = atomicAdd(&g_off[r], 1);
        g_colS[p] = cols[e];
        g_valS[p] = vals[e];
    }
}

// ---------------------------------------------------------------------------
// Build T0: T0[m][b*64+f] = x[b][m][f]
// grid = MM blocks, 128 threads; thread t handles float4 index t of row m
// (c4 = b*16 + f4 == t, since c = b*64 + f)
// ---------------------------------------------------------------------------
__global__ void k_build_T0(const float* __restrict__ x) {
    int m = blockIdx.x;
    int t = threadIdx.x;           // 0..127
    int b  = t >> 4;
    int f4 = t & 15;
    float4 v = reinterpret_cast<const float4*>(x)[((size_t)b * MM + m) * 16 + f4];
    reinterpret_cast<float4*>(&g_T[0][m][0])[t] = v;
}

// ---------------------------------------------------------------------------
// SpMM + Chebyshev combine:
//   Tnext[r] = alpha * (sum_e val*Tcur[col] - Tcur[r]) - beta * Tprev[r]
// One warp per row; each lane owns 4 float4s (16 floats) of the 512-wide row.
// ---------------------------------------------------------------------------
__global__ void __launch_bounds__(256) k_spmm(int kidx, float alpha, float beta) {
    int warp = (blockIdx.x * blockDim.x + threadIdx.x) >> 5;
    int lane = threadIdx.x & 31;
    if (warp >= MM) return;
    int r = warp;

    const float4* Tc4 = reinterpret_cast<const float4*>(&g_T[kidx - 1][0][0]);
    const float4* Tp4 = reinterpret_cast<const float4*>(&g_T[(kidx >= 2) ? kidx - 2 : 0][0][0]);
    float4* Tn4       = reinterpret_cast<float4*>(&g_T[kidx][0][0]);

    float4 acc[4];
    #pragma unroll
    for (int j = 0; j < 4; j++) acc[j] = make_float4(0.f, 0.f, 0.f, 0.f);

    int s = g_rowptr[r], e = g_rowptr[r + 1];
    #pragma unroll 2
    for (int i = s; i < e; i++) {
        float v = __ldg(&g_valS[i]);
        int   c = __ldg(&g_colS[i]);
        const float4* src = Tc4 + (size_t)c * CW4;
        #pragma unroll
        for (int j = 0; j < 4; j++) {
            float4 t = __ldg(&src[lane + 32 * j]);
            acc[j].x += v * t.x;
            acc[j].y += v * t.y;
            acc[j].z += v * t.z;
            acc[j].w += v * t.w;
        }
    }

    const float4* rowc = Tc4 + (size_t)r * CW4;
    const float4* rowp = Tp4 + (size_t)r * CW4;
    float4*       rown = Tn4 + (size_t)r * CW4;
    bool has_beta = (beta != 0.0f);

    #pragma unroll
    for (int j = 0; j < 4; j++) {
        float4 tc = rowc[lane + 32 * j];
        float4 res;
        res.x = alpha * (acc[j].x - tc.x);
        res.y = alpha * (acc[j].y - tc.y);
        res.z = alpha * (acc[j].z - tc.z);
        res.w = alpha * (acc[j].w - tc.w);
        if (has_beta) {
            float4 tp = rowp[lane + 32 * j];
            res.x -= beta * tp.x;
            res.y -= beta * tp.y;
            res.z -= beta * tp.z;
            res.w -= beta * tp.w;
        }
        rown[lane + 32 * j] = res;
    }
}

// ---------------------------------------------------------------------------
// Dense projection: out[b][m][o] = sum_k sum_f Tk[m][b*64+f] * W[f*KK+k][o]
// Block = 64 m-rows x 64 o for one batch b. 256 threads, 4x4 microtile each.
// ---------------------------------------------------------------------------
__global__ void __launch_bounds__(256) k_gemm(const float* __restrict__ W,
                                              float* __restrict__ out) {
    int b  = blockIdx.y;
    int m0 = blockIdx.x * 64;
    int tid = threadIdx.x;
    int tx = tid & 15;     // o / 4
    int ty = tid >> 4;     // m / 4

    __shared__ float As[64][68];   // [f][m], stride 68 (272B: 16B aligned, conflict-free)
    __shared__ float Bs[64][64];   // [f][o]

    float acc[4][4];
    #pragma unroll
    for (int i = 0; i < 4; i++)
        #pragma unroll
        for (int j = 0; j < 4; j++) acc[i][j] = 0.f;

    for (int k = 0; k < KK; k++) {
        const float* Tk = &g_T[k][0][0];

        // Load A tile: As[f][mloc] = Tk[m0+mloc][b*64 + f]
        {
            int f4   = tid >> 4;          // 0..15
            int mbas = tid & 15;          // 0..15
            #pragma unroll
            for (int rr = 0; rr < 4; rr++) {
                int mloc = mbas + rr * 16;
                float4 v = *reinterpret_cast<const float4*>(
                    Tk + (size_t)(m0 + mloc) * CW + b * 64 + f4 * 4);
                As[f4 * 4 + 0][mloc] = v.x;
                As[f4 * 4 + 1][mloc] = v.y;
                As[f4 * 4 + 2][mloc] = v.z;
                As[f4 * 4 + 3][mloc] = v.w;
            }
        }
        // Load B tile: Bs[f][o] = W[(f*KK + k)*64 + o]
        {
            int fb = tid >> 4;
            int o4 = tid & 15;
            #pragma unroll
            for (int rr = 0; rr < 4; rr++) {
                int f = fb + rr * 16;
                float4 w = *reinterpret_cast<const float4*>(
                    W + (size_t)(f * KK + k) * 64 + o4 * 4);
                *reinterpret_cast<float4*>(&Bs[f][o4 * 4]) = w;
            }
        }
        __syncthreads();

        #pragma unroll
        for (int f = 0; f < 64; f++) {
            float4 av = *reinterpret_cast<const float4*>(&As[f][ty * 4]);
            float4 bv = *reinterpret_cast<const float4*>(&Bs[f][tx * 4]);
            float a[4] = {av.x, av.y, av.z, av.w};
            float bb[4] = {bv.x, bv.y, bv.z, bv.w};
            #pragma unroll
            for (int i = 0; i < 4; i++)
                #pragma unroll
                for (int j = 0; j < 4; j++)
                    acc[i][j] += a[i] * bb[j];
        }
        __syncthreads();
    }

    // Epilogue
    #pragma unroll
    for (int i = 0; i < 4; i++) {
        int m = m0 + ty * 4 + i;
        float4 o4v = make_float4(acc[i][0], acc[i][1], acc[i][2], acc[i][3]);
        *reinterpret_cast<float4*>(out + ((size_t)b * MM + m) * 64 + tx * 4) = o4v;
    }
}

// ---------------------------------------------------------------------------
extern "C" void kernel_launch(void* const* d_in, const int* in_sizes, int n_in,
                              void* d_out, int out_size) {
    const float* x  = (const float*)d_in[0];   // [B, M, FIN] f32
    const float* ev = (const float*)d_in[1];   // [NNZ] f32
    const float* W  = (const float*)d_in[2];   // [FIN*K, FOUT] f32
    const int*   er = (const int*)d_in[3];     // [NNZ] int32
    const int*   ec = (const int*)d_in[4];     // [NNZ] int32
    float* out = (float*)d_out;                // [B, M, FOUT] f32

    // CSR build (recomputed every replay; cheap)
    k_zero_counts<<<(MM + 255) / 256, 256>>>();
    k_hist<<<(NNZ + 255) / 256, 256>>>(er);
    k_scan<<<1, 1024>>>();
    k_scatter<<<(NNZ + 255) / 256, 256>>>(er, ec, ev);

    // T0
    k_build_T0<<<MM, 128>>>(x);

    // Chebyshev chain: x1 = Lx0 - x0; xk = 2(Lx_{k-1} - x_{k-1}) - x_{k-2}
    int spmm_blocks = (MM * 32 + 255) / 256;   // one warp per row
    k_spmm<<<spmm_blocks, 256>>>(1, 1.0f, 0.0f);
    for (int k = 2; k < KK; k++)
        k_spmm<<<spmm_blocks, 256>>>(k, 2.0f, 1.0f);

    // Projection
    dim3 ggrid(MM / 64, BB);
    k_gemm<<<ggrid, 256>>>(W, out);
}

// round 3
// speedup vs baseline: 1.4945x; 1.4945x over previous
#include <cuda_runtime.h>
#include <cstdint>

#define BB   8
#define MM   40000
#define FIN  64
#define KK   6
#define FOUT 64
#define NNZ  320000
#define CW   512    // field width = FIN*BB
#define CW4  128    // in float4

// Scratch (static device allocs are the sanctioned workaround)
__device__ float g_T[KK][MM][CW];      // ~491.5 MB: all Chebyshev fields
__device__ int   g_rowptr[MM + 1];
__device__ int   g_counts[MM];
__device__ int   g_off[MM];
__device__ int   g_colS[NNZ];
__device__ float g_valS[NNZ];

// ---------------------------------------------------------------------------
// CSR build
// ---------------------------------------------------------------------------
__global__ void k_zero_counts() {
    int i = blockIdx.x * blockDim.x + threadIdx.x;
    if (i < MM) g_counts[i] = 0;
}

__global__ void k_hist(const int* __restrict__ rows) {
    int e = blockIdx.x * blockDim.x + threadIdx.x;
    if (e < NNZ) atomicAdd(&g_counts[rows[e]], 1);
}

__global__ void k_scan() {
    __shared__ int s[1024];
    const int EPT = (MM + 1023) / 1024;  // 40
    int t = threadIdx.x;
    int base = t * EPT;

    int sum = 0;
    for (int i = 0; i < EPT; i++) {
        int idx = base + i;
        if (idx < MM) sum += g_counts[idx];
    }
    s[t] = sum;
    __syncthreads();

    for (int off = 1; off < 1024; off <<= 1) {
        int v = 0;
        if (t >= off) v = s[t - off];
        __syncthreads();
        s[t] += v;
        __syncthreads();
    }

    int run = s[t] - sum;
    for (int i = 0; i < EPT; i++) {
        int idx = base + i;
        if (idx < MM) {
            int c = g_counts[idx];
            g_rowptr[idx] = run;
            g_off[idx]    = run;
            run += c;
        }
    }
    if (t == 0) g_rowptr[MM] = NNZ;
}

__global__ void k_scatter(const int* __restrict__ rows,
                          const int* __restrict__ cols,
                          const float* __restrict__ vals) {
    int e = blockIdx.x * blockDim.x + threadIdx.x;
    if (e < NNZ) {
        int r = rows[e];
        int p = atomicAdd(&g_off[r], 1);
        g_colS[p] = cols[e];
        g_valS[p] = vals[e];
    }
}

// ---------------------------------------------------------------------------
// Build T0
// ---------------------------------------------------------------------------
__global__ void k_build_T0(const float* __restrict__ x) {
    int m = blockIdx.x;
    int t = threadIdx.x;           // 0..127
    int b  = t >> 4;
    int f4 = t & 15;
    float4 v = reinterpret_cast<const float4*>(x)[((size_t)b * MM + m) * 16 + f4];
    reinterpret_cast<float4*>(&g_T[0][m][0])[t] = v;
}

// ---------------------------------------------------------------------------
// SpMM + Chebyshev combine (one warp per row)
// ---------------------------------------------------------------------------
__global__ void __launch_bounds__(256) k_spmm(int kidx, float alpha, float beta) {
    int warp = (blockIdx.x * blockDim.x + threadIdx.x) >> 5;
    int lane = threadIdx.x & 31;
    if (warp >= MM) return;
    int r = warp;

    const float4* Tc4 = reinterpret_cast<const float4*>(&g_T[kidx - 1][0][0]);
    const float4* Tp4 = reinterpret_cast<const float4*>(&g_T[(kidx >= 2) ? kidx - 2 : 0][0][0]);
    float4* Tn4       = reinterpret_cast<float4*>(&g_T[kidx][0][0]);

    float4 acc[4];
    #pragma unroll
    for (int j = 0; j < 4; j++) acc[j] = make_float4(0.f, 0.f, 0.f, 0.f);

    int s = g_rowptr[r], e = g_rowptr[r + 1];
    #pragma unroll 2
    for (int i = s; i < e; i++) {
        float v = __ldg(&g_valS[i]);
        int   c = __ldg(&g_colS[i]);
        const float4* src = Tc4 + (size_t)c * CW4;
        #pragma unroll
        for (int j = 0; j < 4; j++) {
            float4 t = __ldg(&src[lane + 32 * j]);
            acc[j].x += v * t.x;
            acc[j].y += v * t.y;
            acc[j].z += v * t.z;
            acc[j].w += v * t.w;
        }
    }

    const float4* rowc = Tc4 + (size_t)r * CW4;
    const float4* rowp = Tp4 + (size_t)r * CW4;
    float4*       rown = Tn4 + (size_t)r * CW4;
    bool has_beta = (beta != 0.0f);

    #pragma unroll
    for (int j = 0; j < 4; j++) {
        float4 tc = rowc[lane + 32 * j];
        float4 res;
        res.x = alpha * (acc[j].x - tc.x);
        res.y = alpha * (acc[j].y - tc.y);
        res.z = alpha * (acc[j].z - tc.z);
        res.w = alpha * (acc[j].w - tc.w);
        if (has_beta) {
            float4 tp = rowp[lane + 32 * j];
            res.x -= beta * tp.x;
            res.y -= beta * tp.y;
            res.z -= beta * tp.z;
            res.w -= beta * tp.w;
        }
        rown[lane + 32 * j] = res;
    }
}

// ---------------------------------------------------------------------------
// tf32 tensor-core GEMM: out[b][m][o] = sum_k sum_f Tk[m][b*64+f] * W[f*KK+k][o]
// Block: 128(M) x 64(N), 8 warps as 4x2, warp tile 32x32, mma m16n8k8 tf32.
// ---------------------------------------------------------------------------
#define SA 36   // As row stride: read banks (4g+tg) bijective -> conflict-free
#define SB 72   // Bs row stride (>=64 + pad): read banks (8tg+g) bijective -> conflict-free

__device__ __forceinline__ float to_tf32(float x) {
    uint32_t u;
    asm("cvt.rna.tf32.f32 %0, %1;" : "=r"(u) : "f"(x));
    return __uint_as_float(u);
}

__device__ __forceinline__ void mma_tf32(float* d, const uint32_t* a, const uint32_t* b) {
    asm volatile("mma.sync.aligned.m16n8k8.row.col.f32.tf32.tf32.f32 "
        "{%0,%1,%2,%3}, {%4,%5,%6,%7}, {%8,%9}, {%0,%1,%2,%3};"
        : "+f"(d[0]), "+f"(d[1]), "+f"(d[2]), "+f"(d[3])
        : "r"(a[0]), "r"(a[1]), "r"(a[2]), "r"(a[3]), "r"(b[0]), "r"(b[1]));
}

__global__ void __launch_bounds__(256) k_gemm_tf32(const float* __restrict__ W,
                                                   float* __restrict__ out) {
    __shared__ float As[128 * SA];   // [m][k-chunk of 32]
    __shared__ float Bs[32 * SB];    // [k-chunk of 32][n=64 (+pad)]

    const int b    = blockIdx.y;
    const int m0   = blockIdx.x * 128;
    const int tid  = threadIdx.x;
    const int lane = tid & 31;
    const int warp = tid >> 5;
    const int wm   = warp >> 1;      // 0..3  (M position of warp)
    const int wn   = warp & 1;       // 0..1  (N position of warp)
    const int g    = lane >> 2;      // groupID 0..7
    const int tg   = lane & 3;       // threadID-in-group 0..3

    float acc[2][4][4];
    #pragma unroll
    for (int s = 0; s < 2; s++)
        #pragma unroll
        for (int j = 0; j < 4; j++)
            #pragma unroll
            for (int q = 0; q < 4; q++) acc[s][j][q] = 0.f;

    for (int kf = 0; kf < KK; kf++) {
        const float* Tk = &g_T[kf][0][0] + b * 64;
        #pragma unroll
        for (int fc = 0; fc < 2; fc++) {
            // Load A chunk: 128 rows x 32 f-cols -> As (tf32 converted)
            #pragma unroll
            for (int it = 0; it < 4; it++) {
                int idx = tid + 256 * it;
                int m   = idx >> 3;      // 0..127
                int f4  = idx & 7;       // 0..7
                int mg  = m0 + m; if (mg >= MM) mg = MM - 1;
                float4 v = *reinterpret_cast<const float4*>(
                    Tk + (size_t)mg * CW + fc * 32 + f4 * 4);
                float4 c;
                c.x = to_tf32(v.x); c.y = to_tf32(v.y);
                c.z = to_tf32(v.z); c.w = to_tf32(v.w);
                *reinterpret_cast<float4*>(&As[m * SA + f4 * 4]) = c;
            }
            // Load B chunk: 32 f-rows x 64 o -> Bs (tf32 converted)
            #pragma unroll
            for (int it = 0; it < 2; it++) {
                int idx = tid + 256 * it;
                int f   = idx >> 4;      // 0..31
                int o4  = idx & 15;      // 0..15
                float4 w = *reinterpret_cast<const float4*>(
                    W + (size_t)((fc * 32 + f) * KK + kf) * FOUT + o4 * 4);
                float4 c;
                c.x = to_tf32(w.x); c.y = to_tf32(w.y);
                c.z = to_tf32(w.z); c.w = to_tf32(w.w);
                *reinterpret_cast<float4*>(&Bs[f * SB + o4 * 4]) = c;
            }
            __syncthreads();

            #pragma unroll
            for (int ks = 0; ks < 4; ks++) {
                int kk = ks * 8;
                uint32_t a[2][4];
                #pragma unroll
                for (int s = 0; s < 2; s++) {
                    int mr = wm * 32 + s * 16 + g;
                    a[s][0] = __float_as_uint(As[(mr)     * SA + kk + tg]);
                    a[s][1] = __float_as_uint(As[(mr + 8) * SA + kk + tg]);
                    a[s][2] = __float_as_uint(As[(mr)     * SA + kk + tg + 4]);
                    a[s][3] = __float_as_uint(As[(mr + 8) * SA + kk + tg + 4]);
                }
                #pragma unroll
                for (int j = 0; j < 4; j++) {
                    int n = wn * 32 + j * 8 + g;
                    uint32_t bb[2];
                    bb[0] = __float_as_uint(Bs[(kk + tg)     * SB + n]);
                    bb[1] = __float_as_uint(Bs[(kk + tg + 4) * SB + n]);
                    mma_tf32(acc[0][j], a[0], bb);
                    mma_tf32(acc[1][j], a[1], bb);
                }
            }
            __syncthreads();
        }
    }

    // Epilogue: c0=(g,2tg) c1=(g,2tg+1) c2=(g+8,2tg) c3=(g+8,2tg+1)
    #pragma unroll
    for (int s = 0; s < 2; s++) {
        int mrow = m0 + wm * 32 + s * 16 + g;
        #pragma unroll
        for (int j = 0; j < 4; j++) {
            int n = wn * 32 + j * 8 + 2 * tg;
            if (mrow < MM) {
                float2 v = make_float2(acc[s][j][0], acc[s][j][1]);
                *reinterpret_cast<float2*>(out + ((size_t)b * MM + mrow) * FOUT + n) = v;
            }
            if (mrow + 8 < MM) {
                float2 v = make_float2(acc[s][j][2], acc[s][j][3]);
                *reinterpret_cast<float2*>(out + ((size_t)b * MM + mrow + 8) * FOUT + n) = v;
            }
        }
    }
}

// ---------------------------------------------------------------------------
extern "C" void kernel_launch(void* const* d_in, const int* in_sizes, int n_in,
                              void* d_out, int out_size) {
    const float* x  = (const float*)d_in[0];   // [B, M, FIN] f32
    const float* ev = (const float*)d_in[1];   // [NNZ] f32
    const float* W  = (const float*)d_in[2];   // [FIN*K, FOUT] f32
    const int*   er = (const int*)d_in[3];     // [NNZ] int32
    const int*   ec = (const int*)d_in[4];     // [NNZ] int32
    float* out = (float*)d_out;                // [B, M, FOUT] f32

    // CSR build
    k_zero_counts<<<(MM + 255) / 256, 256>>>();
    k_hist<<<(NNZ + 255) / 256, 256>>>(er);
    k_scan<<<1, 1024>>>();
    k_scatter<<<(NNZ + 255) / 256, 256>>>(er, ec, ev);

    // T0
    k_build_T0<<<MM, 128>>>(x);

    // Chebyshev chain
    int spmm_blocks = (MM * 32 + 255) / 256;
    k_spmm<<<spmm_blocks, 256>>>(1, 1.0f, 0.0f);
    for (int k = 2; k < KK; k++)
        k_spmm<<<spmm_blocks, 256>>>(k, 2.0f, 1.0f);

    // tf32 tensor-core projection
    dim3 ggrid((MM + 127) / 128, BB);
    k_gemm_tf32<<<ggrid, 256>>>(W, out);
}

// round 4
// speedup vs baseline: 2.2932x; 1.5344x over previous
#include <cuda_runtime.h>
#include <cuda_fp16.h>
#include <cstdint>

#define BB   8
#define MM   40000
#define FIN  64
#define KK   6
#define FOUT 64
#define NNZ  320000
#define CW   512    // field width = FIN*BB (halves)
#define CWV  64     // row width in uint4 (8 halves each)

// Scratch (static device allocs are the sanctioned workaround)
__device__ __align__(16) __half g_Th[KK][MM][CW];   // ~245 MB fp16 fields
__device__ int   g_rowptr[MM + 1];
__device__ int   g_counts[MM];
__device__ int   g_off[MM];
__device__ int   g_colS[NNZ];
__device__ float g_valS[NNZ];

// ---------------------------------------------------------------------------
// CSR build
// ---------------------------------------------------------------------------
__global__ void k_zero_counts() {
    int i = blockIdx.x * blockDim.x + threadIdx.x;
    if (i < MM) g_counts[i] = 0;
}

__global__ void k_hist(const int* __restrict__ rows) {
    int e = blockIdx.x * blockDim.x + threadIdx.x;
    if (e < NNZ) atomicAdd(&g_counts[rows[e]], 1);
}

__global__ void k_scan() {
    __shared__ int s[1024];
    const int EPT = (MM + 1023) / 1024;  // 40
    int t = threadIdx.x;
    int base = t * EPT;

    int sum = 0;
    for (int i = 0; i < EPT; i++) {
        int idx = base + i;
        if (idx < MM) sum += g_counts[idx];
    }
    s[t] = sum;
    __syncthreads();

    for (int off = 1; off < 1024; off <<= 1) {
        int v = 0;
        if (t >= off) v = s[t - off];
        __syncthreads();
        s[t] += v;
        __syncthreads();
    }

    int run = s[t] - sum;
    for (int i = 0; i < EPT; i++) {
        int idx = base + i;
        if (idx < MM) {
            int c = g_counts[idx];
            g_rowptr[idx] = run;
            g_off[idx]    = run;
            run += c;
        }
    }
    if (t == 0) g_rowptr[MM] = NNZ;
}

__global__ void k_scatter(const int* __restrict__ rows,
                          const int* __restrict__ cols,
                          const float* __restrict__ vals) {
    int e = blockIdx.x * blockDim.x + threadIdx.x;
    if (e < NNZ) {
        int r = rows[e];
        int p = atomicAdd(&g_off[r], 1);
        g_colS[p] = cols[e];
        g_valS[p] = vals[e];
    }
}

// ---------------------------------------------------------------------------
// Build T0 (fp32 x -> fp16 field): T0[m][b*64+f] = x[b][m][f]
// 4 rows per 256-thread block; 64 threads per row, 8 halves per thread.
// ---------------------------------------------------------------------------
__global__ void __launch_bounds__(256) k_build_T0h(const float* __restrict__ x) {
    int tid = threadIdx.x;
    int m = blockIdx.x * 4 + (tid >> 6);
    int t = tid & 63;                 // 0..63; b = t>>3, f8 = t&7
    int b  = t >> 3;
    int f8 = t & 7;
    const float4* src = reinterpret_cast<const float4*>(
        x + ((size_t)b * MM + m) * 64 + 8 * f8);
    float4 v0 = src[0], v1 = src[1];
    __half2 h0 = __floats2half2_rn(v0.x, v0.y);
    __half2 h1 = __floats2half2_rn(v0.z, v0.w);
    __half2 h2 = __floats2half2_rn(v1.x, v1.y);
    __half2 h3 = __floats2half2_rn(v1.z, v1.w);
    uint4 o;
    o.x = *reinterpret_cast<uint32_t*>(&h0);
    o.y = *reinterpret_cast<uint32_t*>(&h1);
    o.z = *reinterpret_cast<uint32_t*>(&h2);
    o.w = *reinterpret_cast<uint32_t*>(&h3);
    *reinterpret_cast<uint4*>(&g_Th[0][m][8 * t]) = o;
}

// ---------------------------------------------------------------------------
// fp16 SpMM + Chebyshev combine (one warp per row, fp32 accumulation):
//   Tnext[r] = alpha * (sum_e val*Tcur[col] - Tcur[r]) - beta * Tprev[r]
// Lane owns uint4 indices {lane, lane+32} of the 64-uint4 row.
// ---------------------------------------------------------------------------
__device__ __forceinline__ void acc_uint4(float2* acc, uint4 q, float v) {
    const uint32_t w[4] = {q.x, q.y, q.z, q.w};
    #pragma unroll
    for (int i = 0; i < 4; i++) {
        float2 f = __half22float2(*reinterpret_cast<const __half2*>(&w[i]));
        acc[i].x += v * f.x;
        acc[i].y += v * f.y;
    }
}

__device__ __forceinline__ uint4 combine_pack(const float2* acc, uint4 qc, uint4 qp,
                                              float alpha, float beta, bool hb) {
    const uint32_t wc[4] = {qc.x, qc.y, qc.z, qc.w};
    const uint32_t wp[4] = {qp.x, qp.y, qp.z, qp.w};
    uint32_t o[4];
    #pragma unroll
    for (int i = 0; i < 4; i++) {
        float2 c = __half22float2(*reinterpret_cast<const __half2*>(&wc[i]));
        float2 r;
        r.x = alpha * (acc[i].x - c.x);
        r.y = alpha * (acc[i].y - c.y);
        if (hb) {
            float2 p = __half22float2(*reinterpret_cast<const __half2*>(&wp[i]));
            r.x -= beta * p.x;
            r.y -= beta * p.y;
        }
        __half2 h = __float22half2_rn(r);
        o[i] = *reinterpret_cast<uint32_t*>(&h);
    }
    uint4 res; res.x = o[0]; res.y = o[1]; res.z = o[2]; res.w = o[3];
    return res;
}

__global__ void __launch_bounds__(256) k_spmm_h(int kidx, float alpha, float beta) {
    int warp = (blockIdx.x * blockDim.x + threadIdx.x) >> 5;
    int lane = threadIdx.x & 31;
    if (warp >= MM) return;
    int r = warp;

    const uint4* Tc = reinterpret_cast<const uint4*>(&g_Th[kidx - 1][0][0]);
    const uint4* Tp = reinterpret_cast<const uint4*>(&g_Th[(kidx >= 2) ? kidx - 2 : 0][0][0]);
    uint4*       Tn = reinterpret_cast<uint4*>(&g_Th[kidx][0][0]);

    float2 acc[8];
    #pragma unroll
    for (int i = 0; i < 8; i++) acc[i] = make_float2(0.f, 0.f);

    int s = g_rowptr[r], e = g_rowptr[r + 1];
    #pragma unroll 2
    for (int i = s; i < e; i++) {
        float v = __ldg(&g_valS[i]);
        int   c = __ldg(&g_colS[i]);
        const uint4* src = Tc + (size_t)c * CWV;
        uint4 q0 = __ldg(&src[lane]);
        uint4 q1 = __ldg(&src[lane + 32]);
        acc_uint4(acc,     q0, v);
        acc_uint4(acc + 4, q1, v);
    }

    bool hb = (beta != 0.0f);
    const uint4* rowc = Tc + (size_t)r * CWV;
    const uint4* rowp = Tp + (size_t)r * CWV;
    uint4*       rown = Tn + (size_t)r * CWV;

    uint4 c0 = rowc[lane], c1 = rowc[lane + 32];
    uint4 p0 = c0, p1 = c1;
    if (hb) { p0 = rowp[lane]; p1 = rowp[lane + 32]; }

    rown[lane]      = combine_pack(acc,     c0, p0, alpha, beta, hb);
    rown[lane + 32] = combine_pack(acc + 4, c1, p1, alpha, beta, hb);
}

// ---------------------------------------------------------------------------
// fp16 tensor-core GEMM: out[b][m][o] = sum_k sum_f Tk[m][b*64+f] * W[f*KK+k][o]
// Block: 128(M) x 64(N), 8 warps as 4x2, warp tile 32x32, mma m16n8k16 f16.f32.
// As: [m][f-chunk 64], stride 72 halves -> fragment banks (4g+tg) bijective.
// Bs: [o][f] transposed, stride 72 halves -> b-halves contiguous, banks bijective.
// ---------------------------------------------------------------------------
#define SAH 72

__device__ __forceinline__ void mma_f16(float* d, const uint32_t* a,
                                        uint32_t b0, uint32_t b1) {
    asm volatile("mma.sync.aligned.m16n8k16.row.col.f32.f16.f16.f32 "
        "{%0,%1,%2,%3}, {%4,%5,%6,%7}, {%8,%9}, {%0,%1,%2,%3};"
        : "+f"(d[0]), "+f"(d[1]), "+f"(d[2]), "+f"(d[3])
        : "r"(a[0]), "r"(a[1]), "r"(a[2]), "r"(a[3]), "r"(b0), "r"(b1));
}

__global__ void __launch_bounds__(256) k_gemm_f16(const float* __restrict__ W,
                                                  float* __restrict__ out) {
    __shared__ __half As[128 * SAH];   // [m 0..127][f 0..63 (+pad)]
    __shared__ __half Bs[64 * SAH];    // [o 0..63][f 0..63 (+pad)] (transposed W slice)

    const int b    = blockIdx.y;
    const int m0   = blockIdx.x * 128;
    const int tid  = threadIdx.x;
    const int lane = tid & 31;
    const int warp = tid >> 5;
    const int wm   = warp >> 1;      // 0..3
    const int wn   = warp & 1;       // 0..1
    const int g    = lane >> 2;      // 0..7
    const int tg   = lane & 3;       // 0..3

    float acc[2][4][4];
    #pragma unroll
    for (int s = 0; s < 2; s++)
        #pragma unroll
        for (int j = 0; j < 4; j++)
            #pragma unroll
            for (int q = 0; q < 4; q++) acc[s][j][q] = 0.f;

    for (int kf = 0; kf < KK; kf++) {
        // A fill: 128 rows x 64 halves (uint4 granularity, 1024 loads / 256 thr)
        #pragma unroll
        for (int it = 0; it < 4; it++) {
            int idx = tid + 256 * it;
            int m   = idx >> 3;          // 0..127
            int c   = idx & 7;           // 0..7 (uint4 within row)
            int mg  = m0 + m; if (mg >= MM) mg = MM - 1;
            uint4 v = *reinterpret_cast<const uint4*>(&g_Th[kf][mg][b * 64 + 8 * c]);
            *reinterpret_cast<uint4*>(&As[m * SAH + 8 * c]) = v;
        }
        // B fill (transposed): Bs[o][f] = W[(f*KK+kf)*64 + o], fp32 -> fp16
        #pragma unroll
        for (int it = 0; it < 8; it++) {
            int idx = tid + 256 * it;    // 0..2047
            int o   = idx & 63;
            int fp  = idx >> 6;          // 0..31 -> f = 2*fp
            int f   = 2 * fp;
            float w0 = __ldg(&W[(size_t)(f * KK + kf) * FOUT + o]);
            float w1 = __ldg(&W[(size_t)((f + 1) * KK + kf) * FOUT + o]);
            __half2 h = __floats2half2_rn(w0, w1);
            *reinterpret_cast<uint32_t*>(&Bs[o * SAH + f]) =
                *reinterpret_cast<uint32_t*>(&h);
        }
        __syncthreads();

        #pragma unroll
        for (int ks = 0; ks < 4; ks++) {
            int kk = ks * 16;
            uint32_t a[2][4];
            #pragma unroll
            for (int s = 0; s < 2; s++) {
                int mr = wm * 32 + s * 16 + g;
                a[s][0] = *reinterpret_cast<const uint32_t*>(&As[(mr)     * SAH + kk + 2 * tg]);
                a[s][1] = *reinterpret_cast<const uint32_t*>(&As[(mr + 8) * SAH + kk + 2 * tg]);
                a[s][2] = *reinterpret_cast<const uint32_t*>(&As[(mr)     * SAH + kk + 2 * tg + 8]);
                a[s][3] = *reinterpret_cast<const uint32_t*>(&As[(mr + 8) * SAH + kk + 2 * tg + 8]);
            }
            #pragma unroll
            for (int j = 0; j < 4; j++) {
                int n = wn * 32 + j * 8 + g;
                uint32_t b0 = *reinterpret_cast<const uint32_t*>(&Bs[n * SAH + kk + 2 * tg]);
                uint32_t b1 = *reinterpret_cast<const uint32_t*>(&Bs[n * SAH + kk + 2 * tg + 8]);
                mma_f16(acc[0][j], a[0], b0, b1);
                mma_f16(acc[1][j], a[1], b0, b1);
            }
        }
        __syncthreads();
    }

    // Epilogue: c0=(g,2tg) c1=(g,2tg+1) c2=(g+8,2tg) c3=(g+8,2tg+1)
    #pragma unroll
    for (int s = 0; s < 2; s++) {
        int mrow = m0 + wm * 32 + s * 16 + g;
        #pragma unroll
        for (int j = 0; j < 4; j++) {
            int n = wn * 32 + j * 8 + 2 * tg;
            if (mrow < MM) {
                float2 v = make_float2(acc[s][j][0], acc[s][j][1]);
                *reinterpret_cast<float2*>(out + ((size_t)b * MM + mrow) * FOUT + n) = v;
            }
            if (mrow + 8 < MM) {
                float2 v = make_float2(acc[s][j][2], acc[s][j][3]);
                *reinterpret_cast<float2*>(out + ((size_t)b * MM + mrow + 8) * FOUT + n) = v;
            }
        }
    }
}

// ---------------------------------------------------------------------------
extern "C" void kernel_launch(void* const* d_in, const int* in_sizes, int n_in,
                              void* d_out, int out_size) {
    const float* x  = (const float*)d_in[0];   // [B, M, FIN] f32
    const float* ev = (const float*)d_in[1];   // [NNZ] f32
    const float* W  = (const float*)d_in[2];   // [FIN*K, FOUT] f32
    const int*   er = (const int*)d_in[3];     // [NNZ] int32
    const int*   ec = (const int*)d_in[4];     // [NNZ] int32
    float* out = (float*)d_out;                // [B, M, FOUT] f32

    // CSR build
    k_zero_counts<<<(MM + 255) / 256, 256>>>();
    k_hist<<<(NNZ + 255) / 256, 256>>>(er);
    k_scan<<<1, 1024>>>();
    k_scatter<<<(NNZ + 255) / 256, 256>>>(er, ec, ev);

    // T0 (fp16 field)
    k_build_T0h<<<MM / 4, 256>>>(x);

    // Chebyshev chain
    int spmm_blocks = (MM * 32 + 255) / 256;
    k_spmm_h<<<spmm_blocks, 256>>>(1, 1.0f, 0.0f);
    for (int k = 2; k < KK; k++)
        k_spmm_h<<<spmm_blocks, 256>>>(k, 2.0f, 1.0f);

    // fp16 tensor-core projection
    dim3 ggrid((MM + 127) / 128, BB);
    k_gemm_f16<<<ggrid, 256>>>(W, out);
}